// round 12
// baseline (speedup 1.0000x reference)
#include <cuda_runtime.h>

// LocalConvolutionMix: per-pixel local conv, 3x3(pad1) + 5x5(pad2) branches.
// x:  [4, 256, 56, 56] f32
// w1: [4, 1, 32, 9,  56, 56]
// w2: [4, 1, 32, 25, 56, 56]
// out:[4, 2, 1, 256, 56, 56]
//
// Single-wave tiling: grid (4,32,4) = 512 blocks <= 4/SM capacity, so the
// whole kernel is ONE wave (R9 had 1.51 waves; the 0.51 tail ran half-empty).
// Block (28,7)=196 thr; each thread does rows ty and ty+7 as two sequential
// R9 bodies (2 px x 8 groups x 2 branches each) over one 18-row smem tile.
// Depth-1 register pipeline on weight rows + L2 prefetch-ahead (R9 scheme).

#define N_    4
#define C_    256
#define H_    56
#define W_    56
#define WC_   32
#define GPB_  8
#define TH_   14
#define TROWS_ (TH_ + 4)   // 18
#define TW_   28
#define NT_   (TW_ * 7)    // 196 threads
#define HW_   (H_*W_)
#define TCOL_ 64           // interior x[0..55] at cols 4..59; halo 2,3,60,61

#define PF_L2(p) asm volatile("prefetch.global.L2 [%0];" :: "l"(p))

__global__ __launch_bounds__(NT_, 4)
void localconv_mix_kernel(const float* __restrict__ x,
                          const float* __restrict__ w1,
                          const float* __restrict__ w2,
                          float* __restrict__ out)
{
    __shared__ __align__(16) float xs[GPB_][TROWS_][TCOL_];

    const int tx = threadIdx.x;            // 0..27
    const int ty = threadIdx.y;            // 0..6
    const int h0 = blockIdx.x * TH_;
    const int v  = blockIdx.y;             // 0..31
    const int n  = blockIdx.z;

    const int tid = ty * TW_ + tx;         // 0..195

    // ---- stage x tile: 8 g x 18 rows x 14 float4 chunks (interior col 4) ----
    #pragma unroll 1
    for (int e = tid; e < GPB_ * TROWS_ * 14; e += NT_) {
        const int g   = e / (TROWS_ * 14);
        const int rem = e - g * (TROWS_ * 14);
        const int r   = rem / 14;
        const int f4  = rem - r * 14;
        const int hh  = h0 - 2 + r;
        float4 val = make_float4(0.f, 0.f, 0.f, 0.f);
        if (hh >= 0 && hh < H_) {
            const int c = g * WC_ + v;
            val = *(const float4*)(x + (((n * C_ + c) * H_ + hh) * W_ + 4 * f4));
        }
        *(float4*)&xs[g][r][4 + 4 * f4] = val;
    }
    if (tid < GPB_ * TROWS_) {             // 144 < 196: one pass
        const int g = tid / TROWS_;
        const int r = tid - g * TROWS_;
        xs[g][r][2]  = 0.f; xs[g][r][3]  = 0.f;
        xs[g][r][60] = 0.f; xs[g][r][61] = 0.f;
    }

    const int w0 = 2 * tx;
    const int pixA = (h0 + ty) * W_ + w0;          // hrep 0
    const int pixB = (h0 + ty + 7) * W_ + w0;      // hrep 1
    const int wbase2 = (n * WC_ + v) * 25 * HW_;
    const int wbase1 = (n * WC_ + v) * 9  * HW_;

    // prologue L2 prefetch for BOTH h-rows (overlaps staging barrier)
    {
        const float* pA2 = w2 + wbase2 + pixA;
        const float* pB2 = w2 + wbase2 + pixB;
        const float* pA1 = w1 + wbase1 + pixA;
        const float* pB1 = w1 + wbase1 + pixB;
        #pragma unroll
        for (int j = 0; j < 10; j++) { PF_L2(pA2 + (5 + j) * HW_); }
        #pragma unroll
        for (int j = 0; j < 6;  j++) { PF_L2(pA1 + j * HW_); }
        #pragma unroll
        for (int j = 0; j < 10; j++) { PF_L2(pB2 + (5 + j) * HW_); }
        #pragma unroll
        for (int j = 0; j < 6;  j++) { PF_L2(pB1 + j * HW_); }
    }

    __syncthreads();

    #pragma unroll 1
    for (int hrep = 0; hrep < 2; hrep++) {
        const int rbase = ty + 7 * hrep;           // smem row base for window
        const int pix   = hrep ? pixB : pixA;
        const float* w2p = w2 + wbase2 + pix;
        const float* w1p = w1 + wbase1 + pix;

        float2 a1[GPB_], a2[GPB_];
        #pragma unroll
        for (int g = 0; g < GPB_; g++) {
            a1[g] = make_float2(0.f, 0.f);
            a2[g] = make_float2(0.f, 0.f);
        }

        // depth-1 register pipeline: row ki prefetched during ki-1
        float2 w2c[5], w1c[3];
        #pragma unroll
        for (int j = 0; j < 5; j++)
            w2c[j] = __ldg((const float2*)(w2p + j * HW_));

        #pragma unroll
        for (int ki = 0; ki < 5; ki++) {
            float2 w2n[5], w1n[3];
            if (ki < 4) {
                #pragma unroll
                for (int j = 0; j < 5; j++)
                    w2n[j] = __ldg((const float2*)(w2p + ((ki + 1) * 5 + j) * HW_));
                if (ki + 1 >= 1 && ki + 1 <= 3) {
                    #pragma unroll
                    for (int j = 0; j < 3; j++)
                        w1n[j] = __ldg((const float2*)(w1p + (ki * 3 + j) * HW_));
                }
            }
            // keep L2 1-2 rows ahead
            if (ki < 2) {
                #pragma unroll
                for (int j = 0; j < 5; j++) { PF_L2(w2p + ((ki + 3) * 5 + j) * HW_); }
            }
            if (ki == 0) {
                #pragma unroll
                for (int j = 0; j < 3; j++) { PF_L2(w1p + (6 + j) * HW_); }
            }

            const bool mid = (ki >= 1 && ki <= 3);

            #pragma unroll
            for (int g = 0; g < GPB_; g++) {
                // window x[w0-2 .. w0+3] at smem cols w0+2 .. w0+7
                const float* row = &xs[g][rbase + ki][w0 + 2];
                const float2 p01 = *(const float2*)(row + 0);
                const float2 p23 = *(const float2*)(row + 2);
                const float2 p45 = *(const float2*)(row + 4);
                const float x0 = p01.x, x1 = p01.y, x2 = p23.x,
                            x3 = p23.y, x4 = p45.x, x5 = p45.y;

                a2[g].x = fmaf(w2c[0].x, x0, a2[g].x);
                a2[g].y = fmaf(w2c[0].y, x1, a2[g].y);
                a2[g].x = fmaf(w2c[1].x, x1, a2[g].x);
                a2[g].y = fmaf(w2c[1].y, x2, a2[g].y);
                a2[g].x = fmaf(w2c[2].x, x2, a2[g].x);
                a2[g].y = fmaf(w2c[2].y, x3, a2[g].y);
                a2[g].x = fmaf(w2c[3].x, x3, a2[g].x);
                a2[g].y = fmaf(w2c[3].y, x4, a2[g].y);
                a2[g].x = fmaf(w2c[4].x, x4, a2[g].x);
                a2[g].y = fmaf(w2c[4].y, x5, a2[g].y);

                if (mid) {
                    a1[g].x = fmaf(w1c[0].x, x1, a1[g].x);
                    a1[g].y = fmaf(w1c[0].y, x2, a1[g].y);
                    a1[g].x = fmaf(w1c[1].x, x2, a1[g].x);
                    a1[g].y = fmaf(w1c[1].y, x3, a1[g].y);
                    a1[g].x = fmaf(w1c[2].x, x3, a1[g].x);
                    a1[g].y = fmaf(w1c[2].y, x4, a1[g].y);
                }
            }

            #pragma unroll
            for (int j = 0; j < 5; j++) w2c[j] = w2n[j];
            #pragma unroll
            for (int j = 0; j < 3; j++) w1c[j] = w1n[j];
        }

        // streaming stores: output never re-read
        #pragma unroll
        for (int g = 0; g < GPB_; g++) {
            const int c = g * WC_ + v;
            __stcs((float2*)&out[((n * 2 + 0) * C_ + c) * HW_ + pix], a1[g]);
            __stcs((float2*)&out[((n * 2 + 1) * C_ + c) * HW_ + pix], a2[g]);
        }
    }
}

extern "C" void kernel_launch(void* const* d_in, const int* in_sizes, int n_in,
                              void* d_out, int out_size)
{
    const float* x  = (const float*)d_in[0];
    const float* w1 = (const float*)d_in[1];
    const float* w2 = (const float*)d_in[2];
    float* out = (float*)d_out;

    dim3 block(TW_, 7);            // 196 threads
    dim3 grid(H_ / TH_, WC_, N_);  // (4, 32, 4) = 512 blocks -> single wave
    localconv_mix_kernel<<<grid, block>>>(x, w1, w2, out);
}

// round 14
// speedup vs baseline: 1.2297x; 1.2297x over previous
#include <cuda_runtime.h>

// LocalConvolutionMix: per-pixel local conv, 3x3(pad1) + 5x5(pad2) branches.
// x:  [4, 256, 56, 56] f32
// w1: [4, 1, 32, 9,  56, 56]
// w2: [4, 1, 32, 25, 56, 56]
// out:[4, 2, 1, 256, 56, 56]
//
// R9 structure (block (28,8)=224 thr, 2px x 8 groups x 2 branches, weights
// DRAM-once per block, L2 prefetch-ahead) with a DEPTH-2 register pipeline
// on the w2 stream. w1 schedule (FIXED vs R13): row 0 in prologue, row ki
// loaded during ki in {1,2}, rotated after ki in {1,2} -> ki=1,2,3 consume
// rows 0,1,2. 3 blocks/SM -> 896 blocks = 2.02 balanced waves.

#define N_    4
#define C_    256
#define H_    56
#define W_    56
#define WC_   32
#define GPB_  8
#define TH_   8
#define TW_   28
#define HW_   (H_*W_)
#define TCOL_ 64        // smem row: cols 4..59 = x[0..55], halo at 2,3,60,61

#define PF_L2(p) asm volatile("prefetch.global.L2 [%0];" :: "l"(p))

__global__ __launch_bounds__(TW_*TH_, 3)
void localconv_mix_kernel(const float* __restrict__ x,
                          const float* __restrict__ w1,
                          const float* __restrict__ w2,
                          float* __restrict__ out)
{
    __shared__ __align__(16) float xs[GPB_][TH_ + 4][TCOL_];

    const int tx = threadIdx.x;            // 0..27
    const int ty = threadIdx.y;            // 0..7
    const int h0 = blockIdx.x * TH_;
    const int v  = blockIdx.y;             // 0..31
    const int n  = blockIdx.z;

    const int tid = ty * TW_ + tx;         // 0..223

    // ---- stage x tile: aligned float4 interior, zeroed halo cols ----
    {
        const int f4   = tid % 14;         // float4 index in row (0..13)
        const int rowi = tid / 14;         // 0..15
        #pragma unroll
        for (int it = 0; it < 6; it++) {
            const int row = rowi + 16 * it;          // 0..95
            const int g = row / 12;
            const int r = row - g * 12;
            const int hh = h0 - 2 + r;
            float4 val = make_float4(0.f, 0.f, 0.f, 0.f);
            if (hh >= 0 && hh < H_) {
                const int c = g * WC_ + v;
                val = *(const float4*)(x + (((n * C_ + c) * H_ + hh) * W_ + 4 * f4));
            }
            *(float4*)&xs[g][r][4 + 4 * f4] = val;
        }
        if (tid < 96) {
            const int g = tid / 12;
            const int r = tid - g * 12;
            xs[g][r][2]  = 0.f; xs[g][r][3]  = 0.f;
            xs[g][r][60] = 0.f; xs[g][r][61] = 0.f;
        }
    }

    const int h  = h0 + ty;
    const int w0 = 2 * tx;
    const int pix = h * W_ + w0;

    const float* w2p = w2 + (n * WC_ + v) * 25 * HW_ + pix;
    const float* w1p = w1 + (n * WC_ + v) * 9  * HW_ + pix;

    // L2 prefetch ahead of the register pipeline (overlaps staging barrier)
    #pragma unroll
    for (int j = 0; j < 10; j++) { PF_L2(w2p + (10 + j) * HW_); }
    #pragma unroll
    for (int j = 0; j < 6; j++)  { PF_L2(w1p + j * HW_); }

    __syncthreads();

    float2 a1[GPB_], a2[GPB_];
    #pragma unroll
    for (int g = 0; g < GPB_; g++) {
        a1[g] = make_float2(0.f, 0.f);
        a2[g] = make_float2(0.f, 0.f);
    }

    // --- depth-2 pipeline on w2 (rows ki+1, ki+2 in flight), w1 row-exact ---
    float2 w2c[5], w2n[5], w1c[3];
    #pragma unroll
    for (int j = 0; j < 5; j++)
        w2c[j] = __ldg((const float2*)(w2p + j * HW_));          // w2 row 0
    #pragma unroll
    for (int j = 0; j < 5; j++)
        w2n[j] = __ldg((const float2*)(w2p + (5 + j) * HW_));    // w2 row 1
    #pragma unroll
    for (int j = 0; j < 3; j++)
        w1c[j] = __ldg((const float2*)(w1p + j * HW_));          // w1 row 0 (ki=1)

    #pragma unroll
    for (int ki = 0; ki < 5; ki++) {
        float2 w2nn[5], w1n[3];
        if (ki < 3) {
            #pragma unroll
            for (int j = 0; j < 5; j++)
                w2nn[j] = __ldg((const float2*)(w2p + ((ki + 2) * 5 + j) * HW_));
        }
        if (ki == 1 || ki == 2) {              // w1 row ki, consumed at ki+1
            #pragma unroll
            for (int j = 0; j < 3; j++)
                w1n[j] = __ldg((const float2*)(w1p + (ki * 3 + j) * HW_));
        }
        // keep L2 ahead of the register pipeline
        if (ki == 0) {
            #pragma unroll
            for (int j = 0; j < 5; j++) { PF_L2(w2p + (20 + j) * HW_); }
            #pragma unroll
            for (int j = 0; j < 3; j++) { PF_L2(w1p + (6 + j) * HW_); }
        }

        const bool mid = (ki >= 1 && ki <= 3);

        #pragma unroll
        for (int g = 0; g < GPB_; g++) {
            // window x[w0-2 .. w0+3] at smem cols w0+2 .. w0+7 (8B aligned)
            const float* row = &xs[g][ty + ki][w0 + 2];
            const float2 p01 = *(const float2*)(row + 0);
            const float2 p23 = *(const float2*)(row + 2);
            const float2 p45 = *(const float2*)(row + 4);
            const float x0 = p01.x, x1 = p01.y, x2 = p23.x,
                        x3 = p23.y, x4 = p45.x, x5 = p45.y;

            a2[g].x = fmaf(w2c[0].x, x0, a2[g].x);
            a2[g].y = fmaf(w2c[0].y, x1, a2[g].y);
            a2[g].x = fmaf(w2c[1].x, x1, a2[g].x);
            a2[g].y = fmaf(w2c[1].y, x2, a2[g].y);
            a2[g].x = fmaf(w2c[2].x, x2, a2[g].x);
            a2[g].y = fmaf(w2c[2].y, x3, a2[g].y);
            a2[g].x = fmaf(w2c[3].x, x3, a2[g].x);
            a2[g].y = fmaf(w2c[3].y, x4, a2[g].y);
            a2[g].x = fmaf(w2c[4].x, x4, a2[g].x);
            a2[g].y = fmaf(w2c[4].y, x5, a2[g].y);

            if (mid) {
                a1[g].x = fmaf(w1c[0].x, x1, a1[g].x);
                a1[g].y = fmaf(w1c[0].y, x2, a1[g].y);
                a1[g].x = fmaf(w1c[1].x, x2, a1[g].x);
                a1[g].y = fmaf(w1c[1].y, x3, a1[g].y);
                a1[g].x = fmaf(w1c[2].x, x3, a1[g].x);
                a1[g].y = fmaf(w1c[2].y, x4, a1[g].y);
            }
        }

        // rotate pipelines (fully unrolled -> register renames)
        #pragma unroll
        for (int j = 0; j < 5; j++) { w2c[j] = w2n[j]; w2n[j] = w2nn[j]; }
        if (ki == 1 || ki == 2) {
            #pragma unroll
            for (int j = 0; j < 3; j++) w1c[j] = w1n[j];
        }
    }

    // streaming stores: output never re-read, keep L2 for weights
    #pragma unroll
    for (int g = 0; g < GPB_; g++) {
        const int c = g * WC_ + v;
        __stcs((float2*)&out[((n * 2 + 0) * C_ + c) * HW_ + pix], a1[g]);
        __stcs((float2*)&out[((n * 2 + 1) * C_ + c) * HW_ + pix], a2[g]);
    }
}

extern "C" void kernel_launch(void* const* d_in, const int* in_sizes, int n_in,
                              void* d_out, int out_size)
{
    const float* x  = (const float*)d_in[0];
    const float* w1 = (const float*)d_in[1];
    const float* w2 = (const float*)d_in[2];
    float* out = (float*)d_out;

    dim3 block(TW_, TH_);          // 224 threads
    dim3 grid(H_ / TH_, WC_, N_);  // (7, 32, 4) = 896 blocks
    localconv_mix_kernel<<<grid, block>>>(x, w1, w2, out);
}

// round 15
// speedup vs baseline: 1.2466x; 1.0137x over previous
#include <cuda_runtime.h>

// LocalConvolutionMix: per-pixel local conv, 3x3(pad1) + 5x5(pad2) branches.
// x:  [4, 256, 56, 56] f32
// w1: [4, 1, 32, 9,  56, 56]
// w2: [4, 1, 32, 25, 56, 56]
// out:[4, 2, 1, 256, 56, 56]
//
// R14 structure: block (28,8)=224 thr, 2px x 8 groups x 2 branches, weights
// DRAM-once per block, depth-2 register pipeline on w2, row-exact w1
// pipeline, 3 blocks/SM (896 blocks = 2.02 balanced waves).
// This round: evict-first (__ldcs) weight loads so the single-use 54.5MB
// weight stream doesn't evict the 32x-reused x tiles from L2; staging
// reordered (halo zeros first); full-depth prologue L2 prefetch.

#define N_    4
#define C_    256
#define H_    56
#define W_    56
#define WC_   32
#define GPB_  8
#define TH_   8
#define TW_   28
#define HW_   (H_*W_)
#define TCOL_ 64        // smem row: cols 4..59 = x[0..55], halo at 2,3,60,61

#define PF_L2(p) asm volatile("prefetch.global.L2 [%0];" :: "l"(p))

__global__ __launch_bounds__(TW_*TH_, 3)
void localconv_mix_kernel(const float* __restrict__ x,
                          const float* __restrict__ w1,
                          const float* __restrict__ w2,
                          float* __restrict__ out)
{
    __shared__ __align__(16) float xs[GPB_][TH_ + 4][TCOL_];

    const int tx = threadIdx.x;            // 0..27
    const int ty = threadIdx.y;            // 0..7
    const int h0 = blockIdx.x * TH_;
    const int v  = blockIdx.y;             // 0..31
    const int n  = blockIdx.z;

    const int tid = ty * TW_ + tx;         // 0..223

    // ---- halo zeroing first (independent of the x loads) ----
    if (tid < 96) {
        const int g = tid / 12;
        const int r = tid - g * 12;
        xs[g][r][2]  = 0.f; xs[g][r][3]  = 0.f;
        xs[g][r][60] = 0.f; xs[g][r][61] = 0.f;
    }

    // ---- stage x tile: aligned float4 interior (default cache: L2-resident) ----
    {
        const int f4   = tid % 14;         // float4 index in row (0..13)
        const int rowi = tid / 14;         // 0..15
        #pragma unroll
        for (int it = 0; it < 6; it++) {
            const int row = rowi + 16 * it;          // 0..95
            const int g = row / 12;
            const int r = row - g * 12;
            const int hh = h0 - 2 + r;
            float4 val = make_float4(0.f, 0.f, 0.f, 0.f);
            if (hh >= 0 && hh < H_) {
                const int c = g * WC_ + v;
                val = *(const float4*)(x + (((n * C_ + c) * H_ + hh) * W_ + 4 * f4));
            }
            *(float4*)&xs[g][r][4 + 4 * f4] = val;
        }
    }

    const int h  = h0 + ty;
    const int w0 = 2 * tx;
    const int pix = h * W_ + w0;

    const float* w2p = w2 + (n * WC_ + v) * 25 * HW_ + pix;
    const float* w1p = w1 + (n * WC_ + v) * 9  * HW_ + pix;

    // full-depth prologue L2 prefetch (overlaps the staging barrier)
    #pragma unroll
    for (int j = 0; j < 15; j++) { PF_L2(w2p + (10 + j) * HW_); }
    #pragma unroll
    for (int j = 0; j < 9; j++)  { PF_L2(w1p + j * HW_); }

    __syncthreads();

    float2 a1[GPB_], a2[GPB_];
    #pragma unroll
    for (int g = 0; g < GPB_; g++) {
        a1[g] = make_float2(0.f, 0.f);
        a2[g] = make_float2(0.f, 0.f);
    }

    // --- depth-2 pipeline on w2 (rows ki+1, ki+2 in flight), w1 row-exact ---
    // all weight loads evict-first: single-use stream, keep L2 for x/out
    float2 w2c[5], w2n[5], w1c[3];
    #pragma unroll
    for (int j = 0; j < 5; j++)
        w2c[j] = __ldcs((const float2*)(w2p + j * HW_));         // w2 row 0
    #pragma unroll
    for (int j = 0; j < 5; j++)
        w2n[j] = __ldcs((const float2*)(w2p + (5 + j) * HW_));   // w2 row 1
    #pragma unroll
    for (int j = 0; j < 3; j++)
        w1c[j] = __ldcs((const float2*)(w1p + j * HW_));         // w1 row 0 (ki=1)

    #pragma unroll
    for (int ki = 0; ki < 5; ki++) {
        float2 w2nn[5], w1n[3];
        if (ki < 3) {
            #pragma unroll
            for (int j = 0; j < 5; j++)
                w2nn[j] = __ldcs((const float2*)(w2p + ((ki + 2) * 5 + j) * HW_));
        }
        if (ki == 1 || ki == 2) {              // w1 row ki, consumed at ki+1
            #pragma unroll
            for (int j = 0; j < 3; j++)
                w1n[j] = __ldcs((const float2*)(w1p + (ki * 3 + j) * HW_));
        }

        const bool mid = (ki >= 1 && ki <= 3);

        #pragma unroll
        for (int g = 0; g < GPB_; g++) {
            // window x[w0-2 .. w0+3] at smem cols w0+2 .. w0+7 (8B aligned)
            const float* row = &xs[g][ty + ki][w0 + 2];
            const float2 p01 = *(const float2*)(row + 0);
            const float2 p23 = *(const float2*)(row + 2);
            const float2 p45 = *(const float2*)(row + 4);
            const float x0 = p01.x, x1 = p01.y, x2 = p23.x,
                        x3 = p23.y, x4 = p45.x, x5 = p45.y;

            a2[g].x = fmaf(w2c[0].x, x0, a2[g].x);
            a2[g].y = fmaf(w2c[0].y, x1, a2[g].y);
            a2[g].x = fmaf(w2c[1].x, x1, a2[g].x);
            a2[g].y = fmaf(w2c[1].y, x2, a2[g].y);
            a2[g].x = fmaf(w2c[2].x, x2, a2[g].x);
            a2[g].y = fmaf(w2c[2].y, x3, a2[g].y);
            a2[g].x = fmaf(w2c[3].x, x3, a2[g].x);
            a2[g].y = fmaf(w2c[3].y, x4, a2[g].y);
            a2[g].x = fmaf(w2c[4].x, x4, a2[g].x);
            a2[g].y = fmaf(w2c[4].y, x5, a2[g].y);

            if (mid) {
                a1[g].x = fmaf(w1c[0].x, x1, a1[g].x);
                a1[g].y = fmaf(w1c[0].y, x2, a1[g].y);
                a1[g].x = fmaf(w1c[1].x, x2, a1[g].x);
                a1[g].y = fmaf(w1c[1].y, x3, a1[g].y);
                a1[g].x = fmaf(w1c[2].x, x3, a1[g].x);
                a1[g].y = fmaf(w1c[2].y, x4, a1[g].y);
            }
        }

        // rotate pipelines (fully unrolled -> register renames)
        #pragma unroll
        for (int j = 0; j < 5; j++) { w2c[j] = w2n[j]; w2n[j] = w2nn[j]; }
        if (ki == 1 || ki == 2) {
            #pragma unroll
            for (int j = 0; j < 3; j++) w1c[j] = w1n[j];
        }
    }

    // streaming stores: output never re-read, keep L2 for weights/x
    #pragma unroll
    for (int g = 0; g < GPB_; g++) {
        const int c = g * WC_ + v;
        __stcs((float2*)&out[((n * 2 + 0) * C_ + c) * HW_ + pix], a1[g]);
        __stcs((float2*)&out[((n * 2 + 1) * C_ + c) * HW_ + pix], a2[g]);
    }
}

extern "C" void kernel_launch(void* const* d_in, const int* in_sizes, int n_in,
                              void* d_out, int out_size)
{
    const float* x  = (const float*)d_in[0];
    const float* w1 = (const float*)d_in[1];
    const float* w2 = (const float*)d_in[2];
    float* out = (float*)d_out;

    dim3 block(TW_, TH_);          // 224 threads
    dim3 grid(H_ / TH_, WC_, N_);  // (7, 32, 4) = 896 blocks
    localconv_mix_kernel<<<grid, block>>>(x, w1, w2, out);
}